// round 8
// baseline (speedup 1.0000x reference)
#include <cuda_runtime.h>
#include <cstdint>

#define D_DIM 128
#define MAX_N 200064
#define MAX_K 512

typedef unsigned long long u64;

__device__ float g_sums[MAX_K * D_DIM];
__device__ int   g_counts[MAX_K];
__device__ int   g_assign[MAX_N];
__device__ float g_c2[MAX_K];
__device__ float g_f2[MAX_N];

__device__ __forceinline__ void ffma2(u64& acc, u64 a, u64 b) {
    asm("fma.rn.f32x2 %0, %1, %2, %0;" : "+l"(acc) : "l"(a), "l"(b));
}
__device__ __forceinline__ void unpack2(u64 v, float& lo, float& hi) {
    asm("mov.b64 {%0, %1}, %2;" : "=f"(lo), "=f"(hi) : "l"(v));
}

// ---------------------------------------------------------------------------
// Fused prep: zero sums/counts, c2, f2 in one launch.
// Warp w < N  -> f2[w];  warp w in [N, N+K) -> c2[w-N].
// Thread t < KD -> g_sums[t]=0 ; t < K -> g_counts[t]=0.
// ---------------------------------------------------------------------------
__global__ void prep_kernel(const float* __restrict__ F,
                            const float* __restrict__ C, int N, int K) {
    const int t = blockIdx.x * blockDim.x + threadIdx.x;
    const int KD = K * D_DIM;
    if (t < KD) g_sums[t] = 0.0f;
    if (t < K)  g_counts[t] = 0;

    const int w = t >> 5;
    const int lane = t & 31;
    if (w < N) {
        float4 v = reinterpret_cast<const float4*>(F + (size_t)w * D_DIM)[lane];
        float s = v.x * v.x + v.y * v.y + v.z * v.z + v.w * v.w;
        #pragma unroll
        for (int o = 16; o > 0; o >>= 1) s += __shfl_xor_sync(0xffffffffu, s, o);
        if (lane == 0) g_f2[w] = s;
    } else if (w < N + K) {
        int k = w - N;
        float4 v = reinterpret_cast<const float4*>(C + (size_t)k * D_DIM)[lane];
        float s = v.x * v.x + v.y * v.y + v.z * v.z + v.w * v.w;
        #pragma unroll
        for (int o = 16; o > 0; o >>= 1) s += __shfl_xor_sync(0xffffffffu, s, o);
        if (lane == 0) g_c2[k] = s;
    }
}

// ---------------------------------------------------------------------------
// Assignment: 128 pts x 128 centers / block (256 thr), 8x8 microtile,
// D chunked by 8, double-buffered shared. F stored PRE-DUPLICATED in shared
// ({f,f} pairs) so FFMA2 operands need no MOV duplication; C pairs come free
// from float4 register halves. acc[point][center-pair] in packed f32x2.
// ---------------------------------------------------------------------------
#define FPITCH 264   // 256 floats (128 pts duplicated) + 8 pad
#define CPITCH 132   // 128 floats + 4 pad

__global__ __launch_bounds__(256, 2) void assign_kernel(
    const float* __restrict__ F, const float* __restrict__ C, int N, int K)
{
    __shared__ float sF[2][8 * FPITCH];   // duplicated points
    __shared__ float sC[2][8 * CPITCH];

    const int tid = threadIdx.x;
    const int tx  = tid & 15;          // center group 0..15
    const int ty  = tid >> 4;          // point  group 0..15
    const int tx4 = tx * 4;
    const int ty4 = ty * 4;
    const int p0  = blockIdx.x * 128;

    // loader coords
    const int lr  = tid >> 1;          // 0..127 row
    const int lc4 = (tid & 1) * 4;     // 0 or 4 (col group)
    int prow = p0 + lr; if (prow >= N) prow = N - 1;
    const float* Fld = F + (size_t)prow * D_DIM + lc4;

    float bestv[8];
    int   besti[8];
    #pragma unroll
    for (int s = 0; s < 8; s++) { bestv[s] = __int_as_float(0x7f800000); besti[s] = 0; }

    // acc[pp][cp]: point slot pp (0..7) x center-pair cp (0..3)
    u64 acc[8][4];
    #pragma unroll
    for (int i = 0; i < 8; i++)
        #pragma unroll
        for (int j = 0; j < 4; j++) acc[i][j] = 0ULL;

    const int nkt = K >> 7;
    const int it_total = nkt * 16;

    // load + store chunk 0 into buffer 0
    float4 vF = *reinterpret_cast<const float4*>(Fld);
    float4 vC = *reinterpret_cast<const float4*>(C + (size_t)lr * D_DIM + lc4);
    {
        float* dF = sF[0] + lc4 * FPITCH + 2 * lr;
        dF[0 * FPITCH] = vF.x; dF[0 * FPITCH + 1] = vF.x;
        dF[1 * FPITCH] = vF.y; dF[1 * FPITCH + 1] = vF.y;
        dF[2 * FPITCH] = vF.z; dF[2 * FPITCH + 1] = vF.z;
        dF[3 * FPITCH] = vF.w; dF[3 * FPITCH + 1] = vF.w;
        float* dC = sC[0] + lc4 * CPITCH + lr;
        dC[0 * CPITCH] = vC.x; dC[1 * CPITCH] = vC.y;
        dC[2 * CPITCH] = vC.z; dC[3 * CPITCH] = vC.w;
    }
    __syncthreads();

    for (int it = 0; it < it_total; ++it) {
        const int cur   = it & 1;
        const bool more = (it + 1 < it_total);

        if (more) {
            int nit = it + 1;
            int ch  = nit & 15;
            int kt  = nit >> 4;
            vF = *reinterpret_cast<const float4*>(Fld + ch * 8);
            vC = *reinterpret_cast<const float4*>(
                C + (size_t)(kt * 128 + lr) * D_DIM + ch * 8 + lc4);
        }

        #pragma unroll
        for (int d = 0; d < 8; ++d) {
            const float* rowF = sF[cur] + d * FPITCH;
            const float* rowC = sC[cur] + d * CPITCH;
            // F dup pairs: 4 x LDS.128 -> 8 u64 (each = {f,f})
            ulonglong2 f01 = *reinterpret_cast<const ulonglong2*>(rowF + 2 * ty4);
            ulonglong2 f23 = *reinterpret_cast<const ulonglong2*>(rowF + 2 * ty4 + 4);
            ulonglong2 f45 = *reinterpret_cast<const ulonglong2*>(rowF + 128 + 2 * ty4);
            ulonglong2 f67 = *reinterpret_cast<const ulonglong2*>(rowF + 128 + 2 * ty4 + 4);
            // C pairs: 2 x LDS.128 -> 4 u64 (natural pairs)
            ulonglong2 c01 = *reinterpret_cast<const ulonglong2*>(rowC + tx4);
            ulonglong2 c23 = *reinterpret_cast<const ulonglong2*>(rowC + 64 + tx4);
            u64 fd[8] = { f01.x, f01.y, f23.x, f23.y, f45.x, f45.y, f67.x, f67.y };
            u64 cp[4] = { c01.x, c01.y, c23.x, c23.y };
            #pragma unroll
            for (int i = 0; i < 8; i++) {
                ffma2(acc[i][0], fd[i], cp[0]);
                ffma2(acc[i][1], fd[i], cp[1]);
                ffma2(acc[i][2], fd[i], cp[2]);
                ffma2(acc[i][3], fd[i], cp[3]);
            }
        }

        if (more) {
            const int nxt = cur ^ 1;
            float* dF = sF[nxt] + lc4 * FPITCH + 2 * lr;
            dF[0 * FPITCH] = vF.x; dF[0 * FPITCH + 1] = vF.x;
            dF[1 * FPITCH] = vF.y; dF[1 * FPITCH + 1] = vF.y;
            dF[2 * FPITCH] = vF.z; dF[2 * FPITCH + 1] = vF.z;
            dF[3 * FPITCH] = vF.w; dF[3 * FPITCH + 1] = vF.w;
            float* dC = sC[nxt] + lc4 * CPITCH + lr;
            dC[0 * CPITCH] = vC.x; dC[1 * CPITCH] = vC.y;
            dC[2 * CPITCH] = vC.z; dC[3 * CPITCH] = vC.w;
        }
        __syncthreads();

        // k-tile boundary: score + argmin, reset accs
        if ((it & 15) == 15) {
            int kt = it >> 4;
            #pragma unroll
            for (int j = 0; j < 4; j++) {
                // center pair j -> center ids:
                int kbase = kt * 128 + ((j < 2) ? (tx4 + 2 * j) : (64 + tx4 + 2 * (j - 2)));
                float c2a = g_c2[kbase];
                float c2b = g_c2[kbase + 1];
                #pragma unroll
                for (int i = 0; i < 8; i++) {
                    int p = p0 + ((i < 4) ? (ty4 + i) : (64 + ty4 + i - 4));
                    if (p >= N) p = N - 1;
                    float f2p = g_f2[p];
                    float lo, hi;
                    unpack2(acc[i][j], lo, hi);
                    float sa = (f2p - 2.0f * lo) + c2a;
                    float sb = (f2p - 2.0f * hi) + c2b;
                    if (sa < bestv[i]) { bestv[i] = sa; besti[i] = kbase; }
                    if (sb < bestv[i]) { bestv[i] = sb; besti[i] = kbase + 1; }
                    acc[i][j] = 0ULL;
                }
            }
        }
    }

    // reduce across the 16 tx lanes
    #pragma unroll
    for (int s = 0; s < 8; s++) {
        float v  = bestv[s];
        int   ix = besti[s];
        #pragma unroll
        for (int off = 8; off > 0; off >>= 1) {
            float ov = __shfl_down_sync(0xffffffffu, v, off, 16);
            int   oi = __shfl_down_sync(0xffffffffu, ix, off, 16);
            if (ov < v || (ov == v && oi < ix)) { v = ov; ix = oi; }
        }
        if (tx == 0) {
            int p = p0 + ((s < 4) ? (ty4 + s) : (64 + ty4 + s - 4));
            if (p < N) g_assign[p] = ix;
        }
    }
}

// ---------------------------------------------------------------------------
__global__ void seg_kernel(const float* __restrict__ F, int N) {
    int w = (blockIdx.x * blockDim.x + threadIdx.x) >> 5;
    int lane = threadIdx.x & 31;
    if (w >= N) return;
    int a = g_assign[w];
    float4 v = reinterpret_cast<const float4*>(F + (size_t)w * D_DIM)[lane];
    float* dst = g_sums + (size_t)a * D_DIM + lane * 4;
    asm volatile("red.global.add.v4.f32 [%0], {%1, %2, %3, %4};"
                 :: "l"(dst), "f"(v.x), "f"(v.y), "f"(v.z), "f"(v.w)
                 : "memory");
    if (lane == 0) atomicAdd(&g_counts[a], 1);
}

__global__ void final_kernel(float* __restrict__ out, int KD, int nAssign) {
    int i = blockIdx.x * blockDim.x + threadIdx.x;
    if (i < KD) {
        float c = (float)g_counts[i / D_DIM];
        out[i] = g_sums[i] / fmaxf(c, 1.0f);
    } else {
        int a = i - KD;
        if (a < nAssign) out[KD + a] = (float)g_assign[a];
    }
}

// ---------------------------------------------------------------------------
extern "C" void kernel_launch(void* const* d_in, const int* in_sizes, int n_in,
                              void* d_out, int out_size)
{
    (void)n_in;
    const float* F = (const float*)d_in[0];
    const float* C = (const float*)d_in[1];
    const int D = D_DIM;
    const int N = in_sizes[0] / D;
    const int K = in_sizes[1] / D;
    float* out = (float*)d_out;

    const int KD = K * D;

    const int prepThreads = (N + K) * 32;
    prep_kernel<<<(prepThreads + 255) / 256, 256>>>(F, C, N, K);
    assign_kernel<<<(N + 127) / 128, 256>>>(F, C, N, K);
    seg_kernel<<<(N + 7) / 8, 256>>>(F, N);

    int centersPart, assignPart;
    if (out_size >= KD + N)      { centersPart = KD; assignPart = N; }
    else if (out_size >= KD)     { centersPart = KD; assignPart = out_size - KD; }
    else                         { centersPart = 0;  assignPart = out_size; }
    int total = centersPart + assignPart;
    if (total > 0)
        final_kernel<<<(total + 255) / 256, 256>>>(out, centersPart, assignPart);
}

// round 9
// speedup vs baseline: 1.0066x; 1.0066x over previous
#include <cuda_runtime.h>
#include <cstdint>

#define D_DIM 128
#define MAX_N 200064
#define MAX_K 512

typedef unsigned long long u64;

__device__ float g_sums[MAX_K * D_DIM];
__device__ int   g_counts[MAX_K];
__device__ int   g_assign[MAX_N];
__device__ float g_c2[MAX_K];
__device__ float g_f2[MAX_N];

__device__ __forceinline__ void ffma2(u64& acc, u64 a, u64 b) {
    asm("fma.rn.f32x2 %0, %1, %2, %0;" : "+l"(acc) : "l"(a), "l"(b));
}
__device__ __forceinline__ void unpack2(u64 v, float& lo, float& hi) {
    asm("mov.b64 {%0, %1}, %2;" : "=f"(lo), "=f"(hi) : "l"(v));
}

// ---------------------------------------------------------------------------
// Fused prep: zero sums/counts + f2 + c2 in one launch.
// ---------------------------------------------------------------------------
__global__ void prep_kernel(const float* __restrict__ F,
                            const float* __restrict__ C, int N, int K) {
    const int t = blockIdx.x * blockDim.x + threadIdx.x;
    const int KD = K * D_DIM;
    if (t < KD) g_sums[t] = 0.0f;
    if (t < K)  g_counts[t] = 0;

    const int w = t >> 5;
    const int lane = t & 31;
    if (w < N) {
        float4 v = reinterpret_cast<const float4*>(F + (size_t)w * D_DIM)[lane];
        float s = v.x * v.x + v.y * v.y + v.z * v.z + v.w * v.w;
        #pragma unroll
        for (int o = 16; o > 0; o >>= 1) s += __shfl_xor_sync(0xffffffffu, s, o);
        if (lane == 0) g_f2[w] = s;
    } else if (w < N + K) {
        int k = w - N;
        float4 v = reinterpret_cast<const float4*>(C + (size_t)k * D_DIM)[lane];
        float s = v.x * v.x + v.y * v.y + v.z * v.z + v.w * v.w;
        #pragma unroll
        for (int o = 16; o > 0; o >>= 1) s += __shfl_xor_sync(0xffffffffu, s, o);
        if (lane == 0) g_c2[k] = s;
    }
}

// ---------------------------------------------------------------------------
// Assignment: 64 pts x 128 centers per block (256 thr, 16x16), microtile
// 4 pts x 8 centers. FFMA2 lanes pack ADJACENT d-dims: acc = {sum even d,
// sum odd d}; both operands are natural consecutive pairs -> no dup MOVs.
// Shared row-major, pitch 12 floats (48B): LDS.128-aligned, conflict-free.
// Double-buffered, one sync per 8-d chunk. dot = lo+hi at k-tile scoring.
// ---------------------------------------------------------------------------
#define PITCH 12

__global__ __launch_bounds__(256, 2) void assign_kernel(
    const float* __restrict__ F, const float* __restrict__ C, int N, int K)
{
    __shared__ float sF[2][64 * PITCH];
    __shared__ float sC[2][128 * PITCH];

    const int tid = threadIdx.x;
    const int tx  = tid & 15;          // center lane 0..15
    const int ty  = tid >> 4;          // point  lane 0..15
    const int p0  = blockIdx.x * 64;

    // loader coords: row = tid>>1 (0..127), half = tid&1 (4-float group)
    const int lrow = tid >> 1;
    const int lh4  = (tid & 1) * 4;
    int prow = p0 + (lrow & 63); if (prow >= N) prow = N - 1;
    const float* Fld = F + (size_t)prow * D_DIM + lh4;     // + ch*8 at use

    float bestv[4];
    int   besti[4];
    #pragma unroll
    for (int i = 0; i < 4; i++) { bestv[i] = __int_as_float(0x7f800000); besti[i] = 0; }

    u64 acc[4][8];
    #pragma unroll
    for (int i = 0; i < 4; i++)
        #pragma unroll
        for (int j = 0; j < 8; j++) acc[i][j] = 0ULL;

    const int nkt = K >> 7;            // k-tiles of 128 centers
    const int it_total = nkt * 16;     // 16 d-chunks (8 d each) per k-tile

    // load chunk 0 into buffer 0
    float4 vF, vC;
    if (tid < 128) vF = *reinterpret_cast<const float4*>(Fld);
    vC = *reinterpret_cast<const float4*>(C + (size_t)lrow * D_DIM + lh4);
    if (tid < 128)
        *reinterpret_cast<float4*>(sF[0] + lrow * PITCH + lh4) = vF;
    *reinterpret_cast<float4*>(sC[0] + lrow * PITCH + lh4) = vC;
    __syncthreads();

    for (int it = 0; it < it_total; ++it) {
        const int cur   = it & 1;
        const bool more = (it + 1 < it_total);

        if (more) {
            int nit = it + 1;
            int ch  = nit & 15;
            int kt  = nit >> 4;
            if (tid < 128)
                vF = *reinterpret_cast<const float4*>(Fld + ch * 8);
            vC = *reinterpret_cast<const float4*>(
                C + (size_t)(kt * 128 + lrow) * D_DIM + ch * 8 + lh4);
        }

        // compute: two 4-d sub-slices (ds = 0, 4); operands are d-pairs
        #pragma unroll
        for (int ds = 0; ds < 8; ds += 4) {
            ulonglong2 pf[4];
            #pragma unroll
            for (int i = 0; i < 4; i++)
                pf[i] = *reinterpret_cast<const ulonglong2*>(
                    sF[cur] + (ty * 4 + i) * PITCH + ds);
            #pragma unroll
            for (int jg = 0; jg < 2; jg++) {
                ulonglong2 pc[4];
                #pragma unroll
                for (int j4 = 0; j4 < 4; j4++)
                    pc[j4] = *reinterpret_cast<const ulonglong2*>(
                        sC[cur] + (tx + 16 * (jg * 4 + j4)) * PITCH + ds);
                #pragma unroll
                for (int i = 0; i < 4; i++)
                    #pragma unroll
                    for (int j4 = 0; j4 < 4; j4++) {
                        ffma2(acc[i][jg * 4 + j4], pf[i].x, pc[j4].x);
                        ffma2(acc[i][jg * 4 + j4], pf[i].y, pc[j4].y);
                    }
            }
        }

        if (more) {
            const int nxt = cur ^ 1;
            if (tid < 128)
                *reinterpret_cast<float4*>(sF[nxt] + lrow * PITCH + lh4) = vF;
            *reinterpret_cast<float4*>(sC[nxt] + lrow * PITCH + lh4) = vC;
        }
        __syncthreads();

        // k-tile boundary: score + argmin, reset accumulators
        if ((it & 15) == 15) {
            int kt = it >> 4;
            #pragma unroll
            for (int j = 0; j < 8; j++) {
                int k = kt * 128 + tx + 16 * j;
                float c2k = (k < K) ? g_c2[k] : __int_as_float(0x7f800000);
                #pragma unroll
                for (int i = 0; i < 4; i++) {
                    int p = p0 + ty * 4 + i;
                    if (p >= N) p = N - 1;
                    float f2p = g_f2[p];
                    float lo, hi;
                    unpack2(acc[i][j], lo, hi);
                    float dot = lo + hi;
                    float sc = (f2p - 2.0f * dot) + c2k;
                    if (sc < bestv[i]) { bestv[i] = sc; besti[i] = k; }
                    acc[i][j] = 0ULL;
                }
            }
        }
    }

    // reduce min across the 16 tx lanes (contiguous within half-warp)
    #pragma unroll
    for (int i = 0; i < 4; i++) {
        float v  = bestv[i];
        int   ix = besti[i];
        #pragma unroll
        for (int off = 8; off > 0; off >>= 1) {
            float ov = __shfl_down_sync(0xffffffffu, v, off, 16);
            int   oi = __shfl_down_sync(0xffffffffu, ix, off, 16);
            if (ov < v || (ov == v && oi < ix)) { v = ov; ix = oi; }
        }
        if (tx == 0) {
            int p = p0 + ty * 4 + i;
            if (p < N) g_assign[p] = ix;
        }
    }
}

// ---------------------------------------------------------------------------
__global__ void seg_kernel(const float* __restrict__ F, int N) {
    int w = (blockIdx.x * blockDim.x + threadIdx.x) >> 5;
    int lane = threadIdx.x & 31;
    if (w >= N) return;
    int a = g_assign[w];
    float4 v = reinterpret_cast<const float4*>(F + (size_t)w * D_DIM)[lane];
    float* dst = g_sums + (size_t)a * D_DIM + lane * 4;
    asm volatile("red.global.add.v4.f32 [%0], {%1, %2, %3, %4};"
                 :: "l"(dst), "f"(v.x), "f"(v.y), "f"(v.z), "f"(v.w)
                 : "memory");
    if (lane == 0) atomicAdd(&g_counts[a], 1);
}

__global__ void final_kernel(float* __restrict__ out, int KD, int nAssign) {
    int i = blockIdx.x * blockDim.x + threadIdx.x;
    if (i < KD) {
        float c = (float)g_counts[i / D_DIM];
        out[i] = g_sums[i] / fmaxf(c, 1.0f);
    } else {
        int a = i - KD;
        if (a < nAssign) out[KD + a] = (float)g_assign[a];
    }
}

// ---------------------------------------------------------------------------
extern "C" void kernel_launch(void* const* d_in, const int* in_sizes, int n_in,
                              void* d_out, int out_size)
{
    (void)n_in;
    const float* F = (const float*)d_in[0];
    const float* C = (const float*)d_in[1];
    const int D = D_DIM;
    const int N = in_sizes[0] / D;
    const int K = in_sizes[1] / D;
    float* out = (float*)d_out;

    const int KD = K * D;

    const int prepThreads = (N + K) * 32;
    prep_kernel<<<(prepThreads + 255) / 256, 256>>>(F, C, N, K);
    assign_kernel<<<(N + 63) / 64, 256>>>(F, C, N, K);
    seg_kernel<<<(N + 7) / 8, 256>>>(F, N);

    int centersPart, assignPart;
    if (out_size >= KD + N)      { centersPart = KD; assignPart = N; }
    else if (out_size >= KD)     { centersPart = KD; assignPart = out_size - KD; }
    else                         { centersPart = 0;  assignPart = out_size; }
    int total = centersPart + assignPart;
    if (total > 0)
        final_kernel<<<(total + 255) / 256, 256>>>(out, centersPart, assignPart);
}

// round 10
// speedup vs baseline: 1.8690x; 1.8568x over previous
#include <cuda_runtime.h>
#include <cstdint>

#define D_DIM 128
#define MAX_N 200064
#define MAX_K 512

typedef unsigned long long u64;

__device__ float g_sums[MAX_K * D_DIM];
__device__ int   g_counts[MAX_K];
__device__ int   g_assign[MAX_N];
__device__ float g_c2[MAX_K];
__device__ float g_f2[MAX_N];

// ---------------- f32x2 helpers (sm_103a packed fp32) ----------------------
__device__ __forceinline__ u64 pack_dup(float c) {
    u64 r;
    asm("mov.b64 %0, {%1, %1};" : "=l"(r) : "f"(c));
    return r;
}
__device__ __forceinline__ void ffma2(u64& acc, u64 a, u64 b) {
    asm("fma.rn.f32x2 %0, %1, %2, %0;" : "+l"(acc) : "l"(a), "l"(b));
}
__device__ __forceinline__ void unpack2(u64 v, float& lo, float& hi) {
    asm("mov.b64 {%0, %1}, %2;" : "=f"(lo), "=f"(hi) : "l"(v));
}

// ---------------------------------------------------------------------------
// Fused prep: zero sums/counts + f2 + c2 in one launch.
// ---------------------------------------------------------------------------
__global__ void prep_kernel(const float* __restrict__ F,
                            const float* __restrict__ C, int N, int K) {
    const int t = blockIdx.x * blockDim.x + threadIdx.x;
    const int KD = K * D_DIM;
    if (t < KD) g_sums[t] = 0.0f;
    if (t < K)  g_counts[t] = 0;

    const int w = t >> 5;
    const int lane = t & 31;
    if (w < N) {
        float4 v = reinterpret_cast<const float4*>(F + (size_t)w * D_DIM)[lane];
        float s = v.x * v.x + v.y * v.y + v.z * v.z + v.w * v.w;
        #pragma unroll
        for (int o = 16; o > 0; o >>= 1) s += __shfl_xor_sync(0xffffffffu, s, o);
        if (lane == 0) g_f2[w] = s;
    } else if (w < N + K) {
        int k = w - N;
        float4 v = reinterpret_cast<const float4*>(C + (size_t)k * D_DIM)[lane];
        float s = v.x * v.x + v.y * v.y + v.z * v.z + v.w * v.w;
        #pragma unroll
        for (int o = 16; o > 0; o >>= 1) s += __shfl_xor_sync(0xffffffffu, s, o);
        if (lane == 0) g_c2[k] = s;
    }
}

// ---------------------------------------------------------------------------
// Assignment (EXACT R4 configuration — measured 526us, rel_err 9.4e-8):
// 128 pts x 128 centers / block (256 thr), 8x8 microtile, D chunked by 8,
// double-buffered transposed shared tiles (one sync/chunk), packed
// fma.rn.f32x2 over point-pairs, center operands dup'd via MOV.
// ---------------------------------------------------------------------------
#define SPITCH 132

__global__ __launch_bounds__(256, 2) void assign_kernel(
    const float* __restrict__ F, const float* __restrict__ C, int N, int K)
{
    __shared__ float sF[2][8 * SPITCH];
    __shared__ float sC[2][8 * SPITCH];

    const int tid = threadIdx.x;
    const int tx  = tid & 15;          // center group 0..15
    const int ty  = tid >> 4;          // point  group 0..15
    const int tx4 = tx * 4;
    const int ty4 = ty * 4;
    const int p0  = blockIdx.x * 128;

    // loader coords
    const int lr  = tid >> 1;          // 0..127 row
    const int lc4 = (tid & 1) * 4;     // 0 or 4 (col group)
    int prow = p0 + lr; if (prow >= N) prow = N - 1;
    const float* Fld = F + (size_t)prow * D_DIM + lc4;

    float bestv[8];
    int   besti[8];
    #pragma unroll
    for (int s = 0; s < 8; s++) { bestv[s] = __int_as_float(0x7f800000); besti[s] = 0; }

    u64 acc[4][8];
    #pragma unroll
    for (int i = 0; i < 4; i++)
        #pragma unroll
        for (int j = 0; j < 8; j++) acc[i][j] = 0ULL;

    const int nkt = K >> 7;            // k-tiles of 128
    const int it_total = nkt * 16;     // 16 d-chunks each

    // load + store chunk 0 into buffer 0
    float4 vF = *reinterpret_cast<const float4*>(Fld);
    float4 vC = *reinterpret_cast<const float4*>(C + (size_t)lr * D_DIM + lc4);
    {
        float* dF = sF[0] + lc4 * SPITCH + lr;
        dF[0 * SPITCH] = vF.x; dF[1 * SPITCH] = vF.y;
        dF[2 * SPITCH] = vF.z; dF[3 * SPITCH] = vF.w;
        float* dC = sC[0] + lc4 * SPITCH + lr;
        dC[0 * SPITCH] = vC.x; dC[1 * SPITCH] = vC.y;
        dC[2 * SPITCH] = vC.z; dC[3 * SPITCH] = vC.w;
    }
    __syncthreads();

    for (int it = 0; it < it_total; ++it) {
        const int cur  = it & 1;
        const bool more = (it + 1 < it_total);

        // prefetch next chunk (global -> regs), latency overlapped with compute
        if (more) {
            int nit = it + 1;
            int ch  = nit & 15;
            int kt  = nit >> 4;
            vF = *reinterpret_cast<const float4*>(Fld + ch * 8);
            vC = *reinterpret_cast<const float4*>(
                C + (size_t)(kt * 128 + lr) * D_DIM + ch * 8 + lc4);
        }

        // compute this chunk: 8 d-slices from buffer `cur`
        #pragma unroll
        for (int d = 0; d < 8; ++d) {
            const float* rowF = sF[cur] + d * SPITCH;
            const float* rowC = sC[cur] + d * SPITCH;
            ulonglong2 a0 = *reinterpret_cast<const ulonglong2*>(rowF + ty4);
            ulonglong2 a1 = *reinterpret_cast<const ulonglong2*>(rowF + 64 + ty4);
            float4 c0 = *reinterpret_cast<const float4*>(rowC + tx4);
            float4 c1 = *reinterpret_cast<const float4*>(rowC + 64 + tx4);
            u64 cc[8];
            cc[0] = pack_dup(c0.x); cc[1] = pack_dup(c0.y);
            cc[2] = pack_dup(c0.z); cc[3] = pack_dup(c0.w);
            cc[4] = pack_dup(c1.x); cc[5] = pack_dup(c1.y);
            cc[6] = pack_dup(c1.z); cc[7] = pack_dup(c1.w);
            #pragma unroll
            for (int j = 0; j < 8; j++) {
                ffma2(acc[0][j], a0.x, cc[j]);
                ffma2(acc[1][j], a0.y, cc[j]);
                ffma2(acc[2][j], a1.x, cc[j]);
                ffma2(acc[3][j], a1.y, cc[j]);
            }
        }

        // store prefetched chunk into the other buffer
        if (more) {
            const int nxt = cur ^ 1;
            float* dF = sF[nxt] + lc4 * SPITCH + lr;
            dF[0 * SPITCH] = vF.x; dF[1 * SPITCH] = vF.y;
            dF[2 * SPITCH] = vF.z; dF[3 * SPITCH] = vF.w;
            float* dC = sC[nxt] + lc4 * SPITCH + lr;
            dC[0 * SPITCH] = vC.x; dC[1 * SPITCH] = vC.y;
            dC[2 * SPITCH] = vC.z; dC[3 * SPITCH] = vC.w;
        }
        __syncthreads();

        // end of a k-tile: score + argmin, reset accumulators
        if ((it & 15) == 15) {
            int kt = it >> 4;
            #pragma unroll
            for (int j = 0; j < 8; j++) {
                int k = kt * 128 + ((j < 4) ? (tx4 + j) : (64 + tx4 + j - 4));
                float c2k = (k < K) ? g_c2[k] : __int_as_float(0x7f800000);
                #pragma unroll
                for (int pi = 0; pi < 4; pi++) {
                    float lo, hi;
                    unpack2(acc[pi][j], lo, hi);
                    int s0 = (pi >> 1) * 4 + (pi & 1) * 2;
                    int pA = p0 + ((s0 < 4) ? (ty4 + s0) : (64 + ty4 + s0 - 4));
                    int pB = pA + 1;
                    if (pA >= N) pA = N - 1;
                    if (pB >= N) pB = N - 1;
                    float sc0 = (g_f2[pA] - 2.0f * lo) + c2k;
                    float sc1 = (g_f2[pB] - 2.0f * hi) + c2k;
                    if (sc0 < bestv[s0])     { bestv[s0]     = sc0; besti[s0]     = k; }
                    if (sc1 < bestv[s0 + 1]) { bestv[s0 + 1] = sc1; besti[s0 + 1] = k; }
                    acc[pi][j] = 0ULL;
                }
            }
        }
    }

    // reduce across the 16 tx lanes
    #pragma unroll
    for (int s = 0; s < 8; s++) {
        float v  = bestv[s];
        int   ix = besti[s];
        #pragma unroll
        for (int off = 8; off > 0; off >>= 1) {
            float ov = __shfl_down_sync(0xffffffffu, v, off, 16);
            int   oi = __shfl_down_sync(0xffffffffu, ix, off, 16);
            if (ov < v || (ov == v && oi < ix)) { v = ov; ix = oi; }
        }
        if (tx == 0) {
            int p = p0 + ((s < 4) ? (ty4 + s) : (64 + ty4 + s - 4));
            if (p < N) g_assign[p] = ix;
        }
    }
}

// ---------------------------------------------------------------------------
__global__ void seg_kernel(const float* __restrict__ F, int N) {
    int w = (blockIdx.x * blockDim.x + threadIdx.x) >> 5;
    int lane = threadIdx.x & 31;
    if (w >= N) return;
    int a = g_assign[w];
    float4 v = reinterpret_cast<const float4*>(F + (size_t)w * D_DIM)[lane];
    float* dst = g_sums + (size_t)a * D_DIM + lane * 4;
    asm volatile("red.global.add.v4.f32 [%0], {%1, %2, %3, %4};"
                 :: "l"(dst), "f"(v.x), "f"(v.y), "f"(v.z), "f"(v.w)
                 : "memory");
    if (lane == 0) atomicAdd(&g_counts[a], 1);
}

__global__ void final_kernel(float* __restrict__ out, int KD, int nAssign) {
    int i = blockIdx.x * blockDim.x + threadIdx.x;
    if (i < KD) {
        float c = (float)g_counts[i / D_DIM];
        out[i] = g_sums[i] / fmaxf(c, 1.0f);
    } else {
        int a = i - KD;
        if (a < nAssign) out[KD + a] = (float)g_assign[a];
    }
}

// ---------------------------------------------------------------------------
extern "C" void kernel_launch(void* const* d_in, const int* in_sizes, int n_in,
                              void* d_out, int out_size)
{
    (void)n_in;
    const float* F = (const float*)d_in[0];
    const float* C = (const float*)d_in[1];
    const int D = D_DIM;
    const int N = in_sizes[0] / D;
    const int K = in_sizes[1] / D;
    float* out = (float*)d_out;

    const int KD = K * D;

    const int prepThreads = (N + K) * 32;
    prep_kernel<<<(prepThreads + 255) / 256, 256>>>(F, C, N, K);
    assign_kernel<<<(N + 127) / 128, 256>>>(F, C, N, K);
    seg_kernel<<<(N + 7) / 8, 256>>>(F, N);

    int centersPart, assignPart;
    if (out_size >= KD + N)      { centersPart = KD; assignPart = N; }
    else if (out_size >= KD)     { centersPart = KD; assignPart = out_size - KD; }
    else                         { centersPart = 0;  assignPart = out_size; }
    int total = centersPart + assignPart;
    if (total > 0)
        final_kernel<<<(total + 255) / 256, 256>>>(out, centersPart, assignPart);
}